// round 16
// baseline (speedup 1.0000x reference)
#include <cuda_runtime.h>
#include <cuda_fp16.h>
#include <cstdint>

// Problem constants (fixed shapes)
#define B_  4
#define T_  8192
#define D_  1024
#define L_  128
#define H_  16
#define R_  (B_*T_)      // 32768 rows
#define GP_ 8            // split-K partials for G (measured best)

// ---------------- scratch (device globals; allocation-free rule) -------------
__device__ __half g_Xpk[(size_t)R_*D_];     // A-frag X            (64 MB)
__device__ __half g_XT [(size_t)R_*D_];     // B-frag X (contraction=t) (64 MB)
__device__ __half g_Wpk[(size_t)D_*256];    // B-frag [Wk|Wq]      (0.5 MB)
__device__ __half g_ET [(size_t)R_*L_];     // A-frag Em^T per batch (8 MB)
__device__ __half g_Qs [(size_t)R_*L_];     // A-frag softmax(Q)   (8 MB)
__device__ __half g_Z  [(size_t)B_*L_*D_];  // B-frag Z            (1 MB)
__device__ float  g_Gp [(size_t)GP_*B_*L_*D_]; // G partials        (16 MB)
__device__ float  g_Kv [B_*H_*8*64];        // normalized Kv
__device__ float  g_Ksum[B_*L_];

// ---------------- helpers ----------------------------------------------------
// packed f32x2 -> f16x2, lo = a, hi = b (single cvt instruction)
__device__ __forceinline__ uint32_t f2h2(float a, float b){
    uint32_t u;
    asm("cvt.rn.f16x2.f32 %0, %1, %2;" : "=r"(u) : "f"(b), "f"(a));
    return u;
}

__device__ __forceinline__ void cp16(void* dst, const void* src){
    uint32_t d = (uint32_t)__cvta_generic_to_shared(dst);
    asm volatile("cp.async.cg.shared.global [%0], [%1], 16;" :: "r"(d), "l"(src));
}

__device__ __forceinline__ void mma16(float* c,
    uint32_t a0, uint32_t a1, uint32_t a2, uint32_t a3,
    uint32_t b0, uint32_t b1){
    asm volatile("mma.sync.aligned.m16n8k16.row.col.f32.f16.f16.f32 "
                 "{%0,%1,%2,%3}, {%4,%5,%6,%7}, {%8,%9}, {%0,%1,%2,%3};"
                 : "+f"(c[0]), "+f"(c[1]), "+f"(c[2]), "+f"(c[3])
                 : "r"(a0), "r"(a1), "r"(a2), "r"(a3), "r"(b0), "r"(b1));
}

// ---------------- pack v3: vectorized stores, 1 addr calc per uint4 ----------
// Single X read, both outputs (A-frag + XT B-frag), uint4 stores.
__global__ __launch_bounds__(256)
void pack_xc_kernel(const float* __restrict__ X){
    __shared__ float sm[2][16][132];      // 16.9 KB
    const int blk  = blockIdx.x;          // 4096 = (R/64) * (D/128)
    const int Dblk = blk & 7,  Tblk = blk >> 3;
    const int T0 = Tblk*64,  D0 = Dblk*128;
    const int tid = threadIdx.x;
    const int lrow = tid >> 4, lseg = tid & 15;

    #define PLOAD(buf, s) {                                                   \
        const float* src = X + (size_t)(T0 + (s)*16 + lrow)*D_ + D0 + lseg*8; \
        cp16(&sm[buf][lrow][lseg*8],     src);                                \
        cp16(&sm[buf][lrow][lseg*8 + 4], src + 4);                            \
        asm volatile("cp.async.commit_group;" ::: "memory");                  \
    }

    PLOAD(0, 0)
    const int mb = Tblk >> 1;
    const int bb = T0 >> 13;
    uint4* oA = (uint4*)g_Xpk;
    uint4* oB = (uint4*)g_XT;

    // per-thread decompositions (loop-invariant)
    const int kt_l = tid >> 5;                 // A: ktile-local 0..7
    const int r0   = (tid << 2) & 127;         // A: r base (mult of 4)
    const int agr  = r0 >> 4, agc = (r0 >> 2) & 3;
    const int ak0  = kt_l*16 + agc*2;

    const int nsub = tid >> 4;                 // B: 0..15
    const int rr0  = (tid << 2) & 63;          // B: rr base (mult of 4)
    const int bgrD = rr0 >> 3;
    const int bg   = (rr0 >> 1) & 3;           // 0 or 2
    const int Dl   = nsub*8 + bgrD;
    const int tl0  = bg*2;                     // rows tl0, tl0+8, tl0+2, tl0+10

    #pragma unroll
    for (int s = 0; s < 4; ++s){
        if (s < 3){
            PLOAD((s+1)&1, s+1)
            asm volatile("cp.async.wait_group 1;" ::: "memory");
        } else {
            asm volatile("cp.async.wait_group 0;" ::: "memory");
        }
        __syncthreads();
        const float (*smb)[132] = sm[s&1];
        const int msub = (Tblk & 1)*4 + s;

        // A-frag: one uint4 per thread (r0..r0+3 consecutive u32)
        {
            uint4 v;
            v.x = f2h2(smb[agr  ][ak0  ], smb[agr  ][ak0+1]);   // hi8=0,k8=0
            v.y = f2h2(smb[agr  ][ak0+8], smb[agr  ][ak0+9]);   // hi8=0,k8=1
            v.z = f2h2(smb[agr+8][ak0  ], smb[agr+8][ak0+1]);   // hi8=1,k8=0
            v.w = f2h2(smb[agr+8][ak0+8], smb[agr+8][ak0+9]);   // hi8=1,k8=1
            oA[(((size_t)(mb*64 + (D0>>4) + kt_l))*1024 + msub*128 + r0) >> 2] = v;
        }

        // B-frag: one uint4 per thread (bx0..bx0+3 consecutive u32)
        {
            const int ktT = ((T0 + s*16) & 8191) >> 4;
            size_t gB = (((size_t)(bb*8 + Dblk)*512 + ktT)*16)*64;
            uint4 v;
            v.x = f2h2(smb[tl0   ][Dl], smb[tl0+1 ][Dl]);   // gcT=g,   k8T=0
            v.y = f2h2(smb[tl0+8 ][Dl], smb[tl0+9 ][Dl]);   // gcT=g,   k8T=1
            v.z = f2h2(smb[tl0+2 ][Dl], smb[tl0+3 ][Dl]);   // gcT=g+1, k8T=0
            v.w = f2h2(smb[tl0+10][Dl], smb[tl0+11][Dl]);   // gcT=g+1, k8T=1
            oB[(gB + (size_t)tid*4) >> 2] = v;
        }
        __syncthreads();
    }
    #undef PLOAD
}

// ---------------- weights [Wk|Wq] -> B-frag; also zero Ksum ------------------
__global__ void prep_w_kernel(const float* __restrict__ Wk,
                              const float* __restrict__ Wq){
    int i = blockIdx.x * blockDim.x + threadIdx.x;   // 64*256
    if (i < B_*L_) g_Ksum[i] = 0.f;
    int n  = i & 255;
    int kt = i >> 8;
    float f[16];
    #pragma unroll
    for (int j = 0; j < 16; ++j){
        int k = kt*16 + j;
        f[j] = (n < 128) ? Wk[k*L_ + n] : Wq[k*L_ + (n-128)];
    }
    uint32_t arr[8];
    #pragma unroll
    for (int o = 0; o < 8; ++o){
        int gc = o >> 1, k8 = o & 1;
        int j = k8*8 + gc*2;
        arr[o] = f2h2(f[j], f[j+1]);
    }
    int nb = n >> 7, nl = n & 127, nsub = nl >> 3, gr = nl & 7;
    uint32_t* out = (uint32_t*)g_Wpk;
    size_t base = ((size_t)(nb*64 + kt)*16 + nsub)*64 + gr*8;
    *(uint4*)(out + base)     = make_uint4(arr[0], arr[1], arr[2], arr[3]);
    *(uint4*)(out + base + 4) = make_uint4(arr[4], arr[5], arr[6], arr[7]);
}

// ---------------- GEMM1: 128x64 tiles of [K|Q] = X @ [Wk|Wq] -----------------
// nb = blockIdx.x + nbase; nb 0,1 -> E halves (exp*mask -> ET + Ksum);
//                          nb 2,3 -> Q halves (softmax -> Qs).
// BM=128, BN=64, BK=32, 3 stages, 128 threads (4 warps 2x2, warp 64x32).
__global__ __launch_bounds__(128)
void gemm1_kernel(const uint4* __restrict__ Apk, const uint4* __restrict__ Bpk,
                  const float* __restrict__ mask, int nbase){
    __shared__ uint4 SM[2304];        // As 3*512 u4, Bs 3*256 u4 (36 KB)
    uint4* As = SM;
    uint4* Bs = SM + 1536;
    const int tid = threadIdx.x, w = tid >> 5, lane = tid & 31;
    const int nb = blockIdx.x + nbase, mb = blockIdx.y;
    const int wmr = w >> 1, wnc = w & 1;
    const int wmsub = wmr*4;
    const int nb128 = nb >> 1, shalf = nb & 1;
    const uint4* Abase = Apk + (size_t)mb * 16384;

    float c[4][4][4];
    #pragma unroll
    for (int a_ = 0; a_ < 4; a_++)
        #pragma unroll
        for (int b_ = 0; b_ < 4; b_++)
            #pragma unroll
            for (int e_ = 0; e_ < 4; e_++) c[a_][b_][e_] = 0.f;

    #define G1C(buf, it) {                                                    \
        _Pragma("unroll")                                                     \
        for (int p = 0; p < 4; p++)                                           \
            cp16(As + (buf)*512 + p*128 + tid,                                \
                 Abase + (size_t)(it)*512 + p*128 + tid);                     \
        _Pragma("unroll")                                                     \
        for (int kq = 0; kq < 2; kq++)                                        \
            cp16(Bs + (buf)*256 + kq*128 + tid,                               \
                 Bpk + (size_t)(nb128*64 + (it)*2 + kq)*256 + shalf*128 + tid);\
        asm volatile("cp.async.commit_group;" ::: "memory");                  \
    }

    G1C(0, 0)
    G1C(1, 1)

    int buf = 0;
    for (int it = 0; it < 32; ++it){
        asm volatile("cp.async.wait_group 1;" ::: "memory");
        __syncthreads();
        #pragma unroll
        for (int ktl = 0; ktl < 2; ++ktl){
            const uint4* as = &As[buf*512 + ktl*256];
            const uint32_t* bs32 = (const uint32_t*)(Bs + buf*256 + ktl*128);
            uint4 af[4]; uint2 bf[4];
            #pragma unroll
            for (int mi = 0; mi < 4; ++mi)
                af[mi] = as[(wmsub + mi)*32 + lane];
            #pragma unroll
            for (int ni = 0; ni < 4; ++ni)
                bf[ni] = *(const uint2*)(bs32 + (wnc*4 + ni)*64 + lane*2);
            #pragma unroll
            for (int mi = 0; mi < 4; ++mi)
                #pragma unroll
                for (int ni = 0; ni < 4; ++ni)
                    mma16(c[mi][ni], af[mi].x, af[mi].z, af[mi].y, af[mi].w,
                          bf[ni].x, bf[ni].y);
        }
        if (it + 2 < 32){
            int nbuf = buf + 2; if (nbuf >= 3) nbuf -= 3;
            G1C(nbuf, it + 2)
        } else {
            asm volatile("cp.async.commit_group;" ::: "memory");
        }
        buf = (buf + 1 == 3) ? 0 : buf + 1;
    }
    #undef G1C
    asm volatile("cp.async.wait_group 0;" ::: "memory");

    const int gr = lane >> 2, gc = lane & 3;
    const int wm = wmr*64, wn = wnc*32;
    const int b  = mb >> 6;
    __syncthreads();                  // smem free for 16 KB staging

    if (nb < 2){
        unsigned short* sh = (unsigned short*)SM;
        const int gct = gr >> 1, par = gr & 1;
        float kse[4], kso[4];
        #pragma unroll
        for (int ni = 0; ni < 4; ++ni){ kse[ni] = 0.f; kso[ni] = 0.f; }
        #pragma unroll
        for (int mi = 0; mi < 4; ++mi){
            int t0 = mb*128 + wm + mi*16 + gr;
            float m0 = __ldg(mask + t0), m1 = __ldg(mask + t0 + 8);
            int ktl = wmr*4 + mi;
            #pragma unroll
            for (int ni = 0; ni < 4; ++ni){
                int cll = wn + ni*8 + gc*2;
                float v0 = __expf(c[mi][ni][0]) * m0;
                float v1 = __expf(c[mi][ni][1]) * m0;
                float v2 = __expf(c[mi][ni][2]) * m1;
                float v3 = __expf(c[mi][ni][3]) * m1;
                kse[ni] += v0 + v2;
                kso[ni] += v1 + v3;
                int ms = cll >> 4, gh = cll & 7, hi = (cll >> 3) & 1;
                int eb = (ktl*4 + ms)*128 + gh*16 + gct*4 + hi*2;
                sh[(eb     )*2 + par] = __half_as_ushort(__float2half_rn(v0));
                sh[(eb + 16)*2 + par] = __half_as_ushort(__float2half_rn(v1));
                sh[(eb +  1)*2 + par] = __half_as_ushort(__float2half_rn(v2));
                sh[(eb + 17)*2 + par] = __half_as_ushort(__float2half_rn(v3));
            }
        }
        #pragma unroll
        for (int ni = 0; ni < 4; ++ni){
            float se = kse[ni], so = kso[ni];
            se += __shfl_xor_sync(0xffffffffu, se, 4);
            se += __shfl_xor_sync(0xffffffffu, se, 8);
            se += __shfl_xor_sync(0xffffffffu, se, 16);
            so += __shfl_xor_sync(0xffffffffu, so, 4);
            so += __shfl_xor_sync(0xffffffffu, so, 8);
            so += __shfl_xor_sync(0xffffffffu, so, 16);
            if (gr == 0){
                int cl = nb*64 + wn + ni*8 + gc*2;
                atomicAdd(&g_Ksum[b*128 + cl],     se);
                atomicAdd(&g_Ksum[b*128 + cl + 1], so);
            }
        }
        __syncthreads();
        uint4* dstE = ((uint4*)g_ET) + ((size_t)b*512 + (mb & 63)*8)*256;
        #pragma unroll
        for (int i = 0; i < 8; ++i){
            int s = i*128 + tid;
            int blk2 = s >> 5, inner = s & 31;
            int ktl2 = blk2 >> 2, msl = blk2 & 3;
            dstE[(ktl2*8 + nb*4 + msl)*32 + inner] = SM[s];
        }
    } else {
        uint32_t* sw = (uint32_t*)SM;
        #pragma unroll
        for (int mi = 0; mi < 4; ++mi){
            int msubt = wmr*4 + mi;
            #pragma unroll
            for (int ni = 0; ni < 4; ++ni){
                int cll = wn + ni*8 + gc*2;
                float v0 = c[mi][ni][0], v1 = c[mi][ni][1];
                float v2 = c[mi][ni][2], v3 = c[mi][ni][3];
                float mx0 = fmaxf(v0, v1);
                mx0 = fmaxf(mx0, __shfl_xor_sync(0xffffffffu, mx0, 1));
                mx0 = fmaxf(mx0, __shfl_xor_sync(0xffffffffu, mx0, 2));
                float e0 = __expf(v0 - mx0), e1 = __expf(v1 - mx0);
                float s0 = e0 + e1;
                s0 += __shfl_xor_sync(0xffffffffu, s0, 1);
                s0 += __shfl_xor_sync(0xffffffffu, s0, 2);
                float i0 = 1.f / s0;
                float mx1 = fmaxf(v2, v3);
                mx1 = fmaxf(mx1, __shfl_xor_sync(0xffffffffu, mx1, 1));
                mx1 = fmaxf(mx1, __shfl_xor_sync(0xffffffffu, mx1, 2));
                float e2 = __expf(v2 - mx1), e3 = __expf(v3 - mx1);
                float s1 = e2 + e3;
                s1 += __shfl_xor_sync(0xffffffffu, s1, 1);
                s1 += __shfl_xor_sync(0xffffffffu, s1, 2);
                float i1 = 1.f / s1;
                int ktlq = cll >> 4, k8 = ni & 1;
                int idx = (ktlq*8 + msubt)*128 + gr*16 + gc*4 + k8;
                sw[idx]     = f2h2(e0*i0, e1*i0);
                sw[idx + 2] = f2h2(e2*i1, e3*i1);
            }
        }
        __syncthreads();
        uint4* dstQ = ((uint4*)g_Qs) + (size_t)mb*2048 + (size_t)(nb - 2)*1024;
        #pragma unroll
        for (int i = 0; i < 8; ++i) dstQ[i*128 + tid] = SM[i*128 + tid];
    }
}

// =============== GEMM core macro (BM=128,BN=128,BK=32, 3 stages, 128 thr) ====
#define GEMM_CORE(AB, BB, NITER)                                              \
    const int tid  = threadIdx.x;                                             \
    const int w    = tid >> 5;                                                \
    const int lane = tid & 31;                                                \
    const int wmsub = (w >> 1) * 4;                                           \
    const int wnsub = (w & 1) * 8;                                            \
    float c[4][8][4];                                                         \
    _Pragma("unroll")                                                         \
    for (int a_ = 0; a_ < 4; a_++)                                            \
        _Pragma("unroll")                                                     \
        for (int b_ = 0; b_ < 8; b_++)                                        \
            _Pragma("unroll")                                                 \
            for (int e_ = 0; e_ < 4; e_++) c[a_][b_][e_] = 0.f;               \
    {                                                                         \
        _Pragma("unroll")                                                     \
        for (int p = 0; p < 4; p++){                                          \
            cp16(As + p*128 + tid, AB + p*128 + tid);                         \
            cp16(Bs + p*128 + tid, BB + p*128 + tid);                         \
        }                                                                     \
        asm volatile("cp.async.commit_group;" ::: "memory");                  \
        _Pragma("unroll")                                                     \
        for (int p = 0; p < 4; p++){                                          \
            cp16(As + 512 + p*128 + tid, AB + 512 + p*128 + tid);             \
            cp16(Bs + 512 + p*128 + tid, BB + 512 + p*128 + tid);             \
        }                                                                     \
        asm volatile("cp.async.commit_group;" ::: "memory");                  \
    }                                                                         \
    int buf = 0;                                                              \
    for (int it = 0; it < (NITER); ++it){                                     \
        asm volatile("cp.async.wait_group 1;" ::: "memory");                  \
        __syncthreads();                                                      \
        _Pragma("unroll")                                                     \
        for (int ktl = 0; ktl < 2; ++ktl){                                    \
            const uint4* as = &As[buf*512 + ktl*256];                         \
            const uint4* bs = &Bs[buf*512 + ktl*256];                         \
            uint4 af[4]; uint2 bf[8];                                         \
            _Pragma("unroll")                                                 \
            for (int mi = 0; mi < 4; ++mi)                                    \
                af[mi] = as[(wmsub + mi)*32 + lane];                          \
            _Pragma("unroll")                                                 \
            for (int ni = 0; ni < 8; ++ni)                                    \
                bf[ni] = *(const uint2*)((const uint32_t*)bs                  \
                                         + (wnsub + ni)*64 + lane*2);         \
            _Pragma("unroll")                                                 \
            for (int mi = 0; mi < 4; ++mi)                                    \
                _Pragma("unroll")                                             \
                for (int ni = 0; ni < 8; ++ni)                                \
                    mma16(c[mi][ni], af[mi].x, af[mi].z, af[mi].y, af[mi].w,  \
                          bf[ni].x, bf[ni].y);                                \
        }                                                                     \
        if (it + 2 < (NITER)){                                                \
            int nbuf = buf + 2; if (nbuf >= 3) nbuf -= 3;                     \
            const uint4* sa = AB + (size_t)(it+2)*512;                        \
            const uint4* sb = BB + (size_t)(it+2)*512;                        \
            _Pragma("unroll")                                                 \
            for (int p = 0; p < 4; p++){                                      \
                cp16(As + nbuf*512 + p*128 + tid, sa + p*128 + tid);          \
                cp16(Bs + nbuf*512 + p*128 + tid, sb + p*128 + tid);          \
            }                                                                 \
        }                                                                     \
        asm volatile("cp.async.commit_group;" ::: "memory");                  \
        buf = (buf + 1 == 3) ? 0 : buf + 1;                                   \
    }

// ---------------- G partials: Gp[kc] = Em^T @ X over t-chunk kc --------------
__global__ __launch_bounds__(128)
void gemm_g_kernel(const uint4* __restrict__ Apk, const uint4* __restrict__ Bpk){
    __shared__ uint4 SM[3072];
    uint4* As = SM;
    uint4* Bs = SM + 1536;
    const int nb = blockIdx.x;                 // 0..7 (D blocks)
    const int b  = blockIdx.y >> 3, kc = blockIdx.y & 7;
    const uint4* Abase = Apk + ((size_t)b*512 + kc*64)*256;
    const uint4* Bbase = Bpk + (((size_t)(b*8 + nb)*512) + kc*64)*256;

    GEMM_CORE(Abase, Bbase, 32)

    const int gr = lane >> 2, gc = lane & 3;
    const int wm = (w >> 1) * 64, wn = (w & 1) * 64;
    float* Gp = g_Gp + (size_t)kc * (B_*L_*D_);
    #pragma unroll
    for (int mi = 0; mi < 4; ++mi){
        int hl = wm + mi*16 + gr;
        #pragma unroll
        for (int ni = 0; ni < 8; ++ni){
            int Dc = nb*128 + wn + ni*8 + gc*2;
            float* gp = &Gp[((size_t)b*128 + hl)*1024 + Dc];
            *reinterpret_cast<float2*>(gp)
                = make_float2(c[mi][ni][0], c[mi][ni][1]);
            *reinterpret_cast<float2*>(gp + 8*1024)
                = make_float2(c[mi][ni][2], c[mi][ni][3]);
        }
    }
}

// ---------------- Kv = (sum_p Gp @ Wv_head)/Ksum, D-split + smem reduce ------
__global__ __launch_bounds__(256)
void kvz1_kernel(const float* __restrict__ Wv){
    int bh = blockIdx.x;                // b*16 + h
    int b = bh >> 4, h = bh & 15;
    __shared__ float Gs[8][1024];       // 32 KB
    __shared__ float red[4][8][64];     // 8 KB
    int tid = threadIdx.x;
    for (int i = tid; i < 8192; i += 256){
        int l = i >> 10, Dc = i & 1023;
        size_t off = ((size_t)b*128 + h*8 + l)*1024 + Dc;
        float s = 0.f;
        #pragma unroll
        for (int p = 0; p < GP_; ++p)
            s += g_Gp[(size_t)p*(B_*L_*D_) + off];
        Gs[l][Dc] = s;
    }
    __syncthreads();

    int d = tid & 63, lg = tid >> 6;    // lg = Dc quarter
    float acc[8];
    #pragma unroll
    for (int l = 0; l < 8; ++l) acc[l] = 0.f;
    const float* wcol = Wv + h*64 + d;
    #pragma unroll 4
    for (int j = 0; j < 256; ++j){
        int Dc = lg*256 + j;
        float wv = __ldg(wcol + (size_t)Dc*1024);
        #pragma unroll
        for (int l = 0; l < 8; ++l) acc[l] += Gs[l][Dc] * wv;
    }
    #pragma unroll
    for (int l = 0; l < 8; ++l) red[lg][l][d] = acc[l];
    __syncthreads();

    if (tid < 64){
        #pragma unroll
        for (int l = 0; l < 8; ++l){
            float s = red[0][l][tid] + red[1][l][tid]
                    + red[2][l][tid] + red[3][l][tid];
            g_Kv[(bh*8 + l)*64 + tid] = s / g_Ksum[b*128 + h*8 + l];
        }
    }
}

// ---------------- Z[b,(h,l),n] = sum_d Kv[b,h,l,d] * Po[h*64+d, n] -----------
__global__ __launch_bounds__(256)
void z_kernel(const float* __restrict__ Po){
    int bid = blockIdx.x;           // b*64 + h*4 + nc
    int b = bid >> 6, h = (bid >> 2) & 15, nc = bid & 3;
    int tid = threadIdx.x;

    __shared__ float kvn[8][64];
    for (int j = tid; j < 512; j += 256){
        int l = j >> 6, d = j & 63;
        kvn[l][d] = g_Kv[((b*16 + h)*8 + l)*64 + d];
    }
    __syncthreads();

    int n = nc*256 + tid;
    float acc[8];
    #pragma unroll
    for (int l = 0; l < 8; ++l) acc[l] = 0.f;
    for (int d = 0; d < 64; ++d){
        float po = __ldg(Po + (size_t)(h*64 + d)*1024 + n);
        #pragma unroll
        for (int l = 0; l < 8; ++l) acc[l] += kvn[l][d] * po;
    }

    int nbk = n >> 7, nsub = (n & 127) >> 3, gr = n & 7;
    int kt = h >> 1, k8 = h & 1;
    uint32_t* out = (uint32_t*)g_Z;
    size_t base = (((size_t)(b*8 + nbk)*8 + kt)*16 + nsub)*64 + gr*8 + k8;
    #pragma unroll
    for (int j2 = 0; j2 < 4; ++j2)
        out[base + j2*2] = f2h2(acc[2*j2], acc[2*j2+1]);
}

// ---------------- GEMM2: out = Qs @ Z_b  (K=128) -----------------------------
__global__ __launch_bounds__(128)
void gemm2_kernel(const uint4* __restrict__ Apk, const uint4* __restrict__ Bpk,
                  float* __restrict__ C){
    __shared__ uint4 SM[3072];
    uint4* As = SM;
    uint4* Bs = SM + 1536;
    const int nb = blockIdx.x, mb = blockIdx.y;
    const uint4* Abase = Apk + (size_t)mb * 8 * 256;
    const uint4* Bbase = Bpk + (size_t)(mb >> 6) * 16384
                             + (size_t)nb * 8 * 256;

    GEMM_CORE(Abase, Bbase, 4)

    const int gr = lane >> 2, gc = lane & 3;
    const int wm = (w >> 1) * 64, wn = (w & 1) * 64;
    #pragma unroll
    for (int mi = 0; mi < 4; ++mi){
        int r0 = mb*128 + wm + mi*16 + gr;
        #pragma unroll
        for (int ni = 0; ni < 8; ++ni){
            int c0 = nb*128 + wn + ni*8 + gc*2;
            *reinterpret_cast<float2*>(&C[(size_t)r0*D_ + c0])
                = make_float2(c[mi][ni][0], c[mi][ni][1]);
            *reinterpret_cast<float2*>(&C[(size_t)(r0+8)*D_ + c0])
                = make_float2(c[mi][ni][2], c[mi][ni][3]);
        }
    }
}

// ---------------- launch -----------------------------------------------------
extern "C" void kernel_launch(void* const* d_in, const int* in_sizes, int n_in,
                              void* d_out, int out_size){
    const float* X    = (const float*)d_in[0];
    const float* mask = (const float*)d_in[1];
    const float* Wk   = (const float*)d_in[2];
    const float* Wq   = (const float*)d_in[3];
    const float* Wv   = (const float*)d_in[4];
    const float* Po   = (const float*)d_in[5];
    float* out = (float*)d_out;

    void *pXpk, *pXT, *pWpk, *pET, *pQs, *pZ;
    cudaGetSymbolAddress(&pXpk, g_Xpk);
    cudaGetSymbolAddress(&pXT,  g_XT);
    cudaGetSymbolAddress(&pWpk, g_Wpk);
    cudaGetSymbolAddress(&pET,  g_ET);
    cudaGetSymbolAddress(&pQs,  g_Qs);
    cudaGetSymbolAddress(&pZ,   g_Z);

    static cudaStream_t s1 = nullptr;
    static cudaEvent_t evFork = nullptr, evQ = nullptr;
    if (!s1){
        cudaStreamCreateWithFlags(&s1, cudaStreamNonBlocking);
        cudaEventCreateWithFlags(&evFork, cudaEventDisableTiming);
        cudaEventCreateWithFlags(&evQ,   cudaEventDisableTiming);
    }

    pack_xc_kernel<<<(R_/64)*(D_/128), 256>>>(X);
    prep_w_kernel<<<64, 256>>>(Wk, Wq);

    // fork: Q half of GEMM1 runs on side stream; only gemm2 needs its output
    cudaEventRecord(evFork, 0);
    cudaStreamWaitEvent(s1, evFork, 0);
    gemm1_kernel<<<dim3(2, R_/128), 128, 0, s1>>>((const uint4*)pXpk,
                                                  (const uint4*)pWpk, mask, 2);
    cudaEventRecord(evQ, s1);

    // main: E half -> gemm_g -> kvz1 -> z (critical path)
    gemm1_kernel<<<dim3(2, R_/128), 128>>>((const uint4*)pXpk,
                                           (const uint4*)pWpk, mask, 0);

    gemm_g_kernel<<<dim3(8, B_*GP_), 128>>>((const uint4*)pET,
                                            (const uint4*)pXT);

    kvz1_kernel<<<B_*H_, 256>>>(Wv);
    z_kernel<<<B_*H_*4, 256>>>(Po);

    // join: gemm2 needs Qs (side stream) and Z (main)
    cudaStreamWaitEvent(0, evQ, 0);
    gemm2_kernel<<<dim3(8, R_/128), 128>>>((const uint4*)pQs,
                                           (const uint4*)pZ, out);
}

// round 17
// speedup vs baseline: 1.1554x; 1.1554x over previous
#include <cuda_runtime.h>
#include <cuda_fp16.h>
#include <cstdint>

// Problem constants (fixed shapes)
#define B_  4
#define T_  8192
#define D_  1024
#define L_  128
#define H_  16
#define R_  (B_*T_)      // 32768 rows
#define GP_ 8            // split-K partials for G (measured best)

// ---------------- scratch (device globals; allocation-free rule) -------------
__device__ __half g_Xpk[(size_t)R_*D_];     // A-frag X            (64 MB)
__device__ __half g_XT [(size_t)R_*D_];     // B-frag X (contraction=t) (64 MB)
__device__ __half g_Wpk[(size_t)D_*256];    // B-frag [Wk|Wq]      (0.5 MB)
__device__ __half g_ET [(size_t)R_*L_];     // A-frag Em^T per batch (8 MB)
__device__ __half g_Qs [(size_t)R_*L_];     // A-frag softmax(Q)   (8 MB)
__device__ __half g_Z  [(size_t)B_*L_*D_];  // B-frag Z            (1 MB)
__device__ float  g_Gp [(size_t)GP_*B_*L_*D_]; // G partials        (16 MB)
__device__ float  g_Kv [B_*H_*8*64];        // UNnormalized Kv (atomic)
__device__ float  g_Ksum[B_*L_];

// ---------------- helpers ----------------------------------------------------
// packed f32x2 -> f16x2, lo = a, hi = b (single cvt instruction)
__device__ __forceinline__ uint32_t f2h2(float a, float b){
    uint32_t u;
    asm("cvt.rn.f16x2.f32 %0, %1, %2;" : "=r"(u) : "f"(b), "f"(a));
    return u;
}

__device__ __forceinline__ void cp16(void* dst, const void* src){
    uint32_t d = (uint32_t)__cvta_generic_to_shared(dst);
    asm volatile("cp.async.cg.shared.global [%0], [%1], 16;" :: "r"(d), "l"(src));
}

__device__ __forceinline__ void mma16(float* c,
    uint32_t a0, uint32_t a1, uint32_t a2, uint32_t a3,
    uint32_t b0, uint32_t b1){
    asm volatile("mma.sync.aligned.m16n8k16.row.col.f32.f16.f16.f32 "
                 "{%0,%1,%2,%3}, {%4,%5,%6,%7}, {%8,%9}, {%0,%1,%2,%3};"
                 : "+f"(c[0]), "+f"(c[1]), "+f"(c[2]), "+f"(c[3])
                 : "r"(a0), "r"(a1), "r"(a2), "r"(a3), "r"(b0), "r"(b1));
}

// ---------------- pack v2: cp.async pipelined, 4 subtiles (64 rows) per CTA --
// Single X read, both outputs (A-frag + XT B-frag).
__global__ __launch_bounds__(256)
void pack_xc_kernel(const float* __restrict__ X){
    __shared__ float sm[2][16][132];      // 16.9 KB, 16B-aligned rows
    const int blk  = blockIdx.x;          // 4096 = (R/64) * (D/128)
    const int Dblk = blk & 7,  Tblk = blk >> 3;
    const int T0 = Tblk*64,  D0 = Dblk*128;
    const int tid = threadIdx.x;
    const int lrow = tid >> 4, lseg = tid & 15;

    #define PLOAD(buf, s) {                                                   \
        const float* src = X + (size_t)(T0 + (s)*16 + lrow)*D_ + D0 + lseg*8; \
        cp16(&sm[buf][lrow][lseg*8],     src);                                \
        cp16(&sm[buf][lrow][lseg*8 + 4], src + 4);                            \
        asm volatile("cp.async.commit_group;" ::: "memory");                  \
    }

    PLOAD(0, 0)
    const int mb = Tblk >> 1;
    const int bb = T0 >> 13;
    uint32_t* oA = (uint32_t*)g_Xpk;
    uint32_t* oB = (uint32_t*)g_XT;

    #pragma unroll
    for (int s = 0; s < 4; ++s){
        if (s < 3){
            PLOAD((s+1)&1, s+1)
            asm volatile("cp.async.wait_group 1;" ::: "memory");
        } else {
            asm volatile("cp.async.wait_group 0;" ::: "memory");
        }
        __syncthreads();
        const float (*smb)[132] = sm[s&1];
        const int msub = (Tblk & 1)*4 + s;

        // A-frag: m=t(16 rows), k=D(128)
        #pragma unroll
        for (int q = 0; q < 4; ++q){
            int a = q*256 + tid;           // 0..1023
            int kt_l = a >> 7, r = a & 127;
            int gr = r >> 4, gc = (r >> 2) & 3, hi8 = (r >> 1) & 1, k8 = r & 1;
            int m = hi8*8 + gr;
            int k = kt_l*16 + k8*8 + gc*2;
            oA[(size_t)(mb*64 + (D0>>4) + kt_l)*1024 + msub*128 + r]
                = f2h2(smb[m][k], smb[m][k+1]);
        }
        // B-frag: k=t(16), n=D(128) -> 1024 contiguous b32
        const int ktT = ((T0 + s*16) & 8191) >> 4;
        size_t gB = (((size_t)(bb*8 + Dblk)*512 + ktT)*16)*64;
        #pragma unroll
        for (int q = 0; q < 4; ++q){
            int bx = q*256 + tid;          // 0..1023
            int nsub = bx >> 6, rr = bx & 63;
            int grD = rr >> 3, gcT = (rr >> 1) & 3, k8T = rr & 1;
            int Dl = nsub*8 + grD;
            int tl = k8T*8 + gcT*2;
            oB[gB + bx] = f2h2(smb[tl][Dl], smb[tl+1][Dl]);
        }
        __syncthreads();
    }
    #undef PLOAD
}

// ---------------- weights [Wk|Wq] -> B-frag; zero Ksum + Kv ------------------
__global__ void prep_w_kernel(const float* __restrict__ Wk,
                              const float* __restrict__ Wq){
    int i = blockIdx.x * blockDim.x + threadIdx.x;   // 64*256 = 16384
    if (i < B_*L_) g_Ksum[i] = 0.f;
    g_Kv[i] = 0.f;
    g_Kv[i + 16384] = 0.f;
    int n  = i & 255;
    int kt = i >> 8;
    float f[16];
    #pragma unroll
    for (int j = 0; j < 16; ++j){
        int k = kt*16 + j;
        f[j] = (n < 128) ? Wk[k*L_ + n] : Wq[k*L_ + (n-128)];
    }
    uint32_t arr[8];
    #pragma unroll
    for (int o = 0; o < 8; ++o){
        int gc = o >> 1, k8 = o & 1;
        int j = k8*8 + gc*2;
        arr[o] = f2h2(f[j], f[j+1]);
    }
    int nb = n >> 7, nl = n & 127, nsub = nl >> 3, gr = nl & 7;
    uint32_t* out = (uint32_t*)g_Wpk;
    size_t base = ((size_t)(nb*64 + kt)*16 + nsub)*64 + gr*8;
    *(uint4*)(out + base)     = make_uint4(arr[0], arr[1], arr[2], arr[3]);
    *(uint4*)(out + base + 4) = make_uint4(arr[4], arr[5], arr[6], arr[7]);
}

// ---------------- GEMM1: 128x64 tiles of [K|Q] = X @ [Wk|Wq] -----------------
// nb = blockIdx.x + nbase; nb 0,1 -> E halves (exp*mask -> ET + Ksum);
//                          nb 2,3 -> Q halves (softmax -> Qs).
// BM=128, BN=64, BK=32, 3 stages, 128 threads (4 warps 2x2, warp 64x32).
__global__ __launch_bounds__(128)
void gemm1_kernel(const uint4* __restrict__ Apk, const uint4* __restrict__ Bpk,
                  const float* __restrict__ mask, int nbase){
    __shared__ uint4 SM[2304];        // As 3*512 u4, Bs 3*256 u4 (36 KB)
    uint4* As = SM;
    uint4* Bs = SM + 1536;
    const int tid = threadIdx.x, w = tid >> 5, lane = tid & 31;
    const int nb = blockIdx.x + nbase, mb = blockIdx.y;
    const int wmr = w >> 1, wnc = w & 1;
    const int wmsub = wmr*4;
    const int nb128 = nb >> 1, shalf = nb & 1;
    const uint4* Abase = Apk + (size_t)mb * 16384;

    float c[4][4][4];
    #pragma unroll
    for (int a_ = 0; a_ < 4; a_++)
        #pragma unroll
        for (int b_ = 0; b_ < 4; b_++)
            #pragma unroll
            for (int e_ = 0; e_ < 4; e_++) c[a_][b_][e_] = 0.f;

    #define G1C(buf, it) {                                                    \
        _Pragma("unroll")                                                     \
        for (int p = 0; p < 4; p++)                                           \
            cp16(As + (buf)*512 + p*128 + tid,                                \
                 Abase + (size_t)(it)*512 + p*128 + tid);                     \
        _Pragma("unroll")                                                     \
        for (int kq = 0; kq < 2; kq++)                                        \
            cp16(Bs + (buf)*256 + kq*128 + tid,                               \
                 Bpk + (size_t)(nb128*64 + (it)*2 + kq)*256 + shalf*128 + tid);\
        asm volatile("cp.async.commit_group;" ::: "memory");                  \
    }

    G1C(0, 0)
    G1C(1, 1)

    int buf = 0;
    for (int it = 0; it < 32; ++it){
        asm volatile("cp.async.wait_group 1;" ::: "memory");
        __syncthreads();
        #pragma unroll
        for (int ktl = 0; ktl < 2; ++ktl){
            const uint4* as = &As[buf*512 + ktl*256];
            const uint32_t* bs32 = (const uint32_t*)(Bs + buf*256 + ktl*128);
            uint4 af[4]; uint2 bf[4];
            #pragma unroll
            for (int mi = 0; mi < 4; ++mi)
                af[mi] = as[(wmsub + mi)*32 + lane];
            #pragma unroll
            for (int ni = 0; ni < 4; ++ni)
                bf[ni] = *(const uint2*)(bs32 + (wnc*4 + ni)*64 + lane*2);
            #pragma unroll
            for (int mi = 0; mi < 4; ++mi)
                #pragma unroll
                for (int ni = 0; ni < 4; ++ni)
                    mma16(c[mi][ni], af[mi].x, af[mi].z, af[mi].y, af[mi].w,
                          bf[ni].x, bf[ni].y);
        }
        if (it + 2 < 32){
            int nbuf = buf + 2; if (nbuf >= 3) nbuf -= 3;
            G1C(nbuf, it + 2)
        } else {
            asm volatile("cp.async.commit_group;" ::: "memory");
        }
        buf = (buf + 1 == 3) ? 0 : buf + 1;
    }
    #undef G1C
    asm volatile("cp.async.wait_group 0;" ::: "memory");

    const int gr = lane >> 2, gc = lane & 3;
    const int wm = wmr*64, wn = wnc*32;
    const int b  = mb >> 6;
    __syncthreads();                  // smem free for 16 KB staging

    if (nb < 2){
        unsigned short* sh = (unsigned short*)SM;
        const int gct = gr >> 1, par = gr & 1;
        float kse[4], kso[4];
        #pragma unroll
        for (int ni = 0; ni < 4; ++ni){ kse[ni] = 0.f; kso[ni] = 0.f; }
        #pragma unroll
        for (int mi = 0; mi < 4; ++mi){
            int t0 = mb*128 + wm + mi*16 + gr;
            float m0 = __ldg(mask + t0), m1 = __ldg(mask + t0 + 8);
            int ktl = wmr*4 + mi;
            #pragma unroll
            for (int ni = 0; ni < 4; ++ni){
                int cll = wn + ni*8 + gc*2;
                float v0 = __expf(c[mi][ni][0]) * m0;
                float v1 = __expf(c[mi][ni][1]) * m0;
                float v2 = __expf(c[mi][ni][2]) * m1;
                float v3 = __expf(c[mi][ni][3]) * m1;
                kse[ni] += v0 + v2;
                kso[ni] += v1 + v3;
                int ms = cll >> 4, gh = cll & 7, hi = (cll >> 3) & 1;
                int eb = (ktl*4 + ms)*128 + gh*16 + gct*4 + hi*2;
                sh[(eb     )*2 + par] = __half_as_ushort(__float2half_rn(v0));
                sh[(eb + 16)*2 + par] = __half_as_ushort(__float2half_rn(v1));
                sh[(eb +  1)*2 + par] = __half_as_ushort(__float2half_rn(v2));
                sh[(eb + 17)*2 + par] = __half_as_ushort(__float2half_rn(v3));
            }
        }
        #pragma unroll
        for (int ni = 0; ni < 4; ++ni){
            float se = kse[ni], so = kso[ni];
            se += __shfl_xor_sync(0xffffffffu, se, 4);
            se += __shfl_xor_sync(0xffffffffu, se, 8);
            se += __shfl_xor_sync(0xffffffffu, se, 16);
            so += __shfl_xor_sync(0xffffffffu, so, 4);
            so += __shfl_xor_sync(0xffffffffu, so, 8);
            so += __shfl_xor_sync(0xffffffffu, so, 16);
            if (gr == 0){
                int cl = nb*64 + wn + ni*8 + gc*2;
                atomicAdd(&g_Ksum[b*128 + cl],     se);
                atomicAdd(&g_Ksum[b*128 + cl + 1], so);
            }
        }
        __syncthreads();
        uint4* dstE = ((uint4*)g_ET) + ((size_t)b*512 + (mb & 63)*8)*256;
        #pragma unroll
        for (int i = 0; i < 8; ++i){
            int s = i*128 + tid;
            int blk2 = s >> 5, inner = s & 31;
            int ktl2 = blk2 >> 2, msl = blk2 & 3;
            dstE[(ktl2*8 + nb*4 + msl)*32 + inner] = SM[s];
        }
    } else {
        uint32_t* sw = (uint32_t*)SM;
        #pragma unroll
        for (int mi = 0; mi < 4; ++mi){
            int msubt = wmr*4 + mi;
            #pragma unroll
            for (int ni = 0; ni < 4; ++ni){
                int cll = wn + ni*8 + gc*2;
                float v0 = c[mi][ni][0], v1 = c[mi][ni][1];
                float v2 = c[mi][ni][2], v3 = c[mi][ni][3];
                float mx0 = fmaxf(v0, v1);
                mx0 = fmaxf(mx0, __shfl_xor_sync(0xffffffffu, mx0, 1));
                mx0 = fmaxf(mx0, __shfl_xor_sync(0xffffffffu, mx0, 2));
                float e0 = __expf(v0 - mx0), e1 = __expf(v1 - mx0);
                float s0 = e0 + e1;
                s0 += __shfl_xor_sync(0xffffffffu, s0, 1);
                s0 += __shfl_xor_sync(0xffffffffu, s0, 2);
                float i0 = 1.f / s0;
                float mx1 = fmaxf(v2, v3);
                mx1 = fmaxf(mx1, __shfl_xor_sync(0xffffffffu, mx1, 1));
                mx1 = fmaxf(mx1, __shfl_xor_sync(0xffffffffu, mx1, 2));
                float e2 = __expf(v2 - mx1), e3 = __expf(v3 - mx1);
                float s1 = e2 + e3;
                s1 += __shfl_xor_sync(0xffffffffu, s1, 1);
                s1 += __shfl_xor_sync(0xffffffffu, s1, 2);
                float i1 = 1.f / s1;
                int ktlq = cll >> 4, k8 = ni & 1;
                int idx = (ktlq*8 + msubt)*128 + gr*16 + gc*4 + k8;
                sw[idx]     = f2h2(e0*i0, e1*i0);
                sw[idx + 2] = f2h2(e2*i1, e3*i1);
            }
        }
        __syncthreads();
        uint4* dstQ = ((uint4*)g_Qs) + (size_t)mb*2048 + (size_t)(nb - 2)*1024;
        #pragma unroll
        for (int i = 0; i < 8; ++i) dstQ[i*128 + tid] = SM[i*128 + tid];
    }
}

// =============== GEMM core macro (BM=128,BN=128,BK=32, 3 stages, 128 thr) ====
#define GEMM_CORE(AB, BB, NITER)                                              \
    const int tid  = threadIdx.x;                                             \
    const int w    = tid >> 5;                                                \
    const int lane = tid & 31;                                                \
    const int wmsub = (w >> 1) * 4;                                           \
    const int wnsub = (w & 1) * 8;                                            \
    float c[4][8][4];                                                         \
    _Pragma("unroll")                                                         \
    for (int a_ = 0; a_ < 4; a_++)                                            \
        _Pragma("unroll")                                                     \
        for (int b_ = 0; b_ < 8; b_++)                                        \
            _Pragma("unroll")                                                 \
            for (int e_ = 0; e_ < 4; e_++) c[a_][b_][e_] = 0.f;               \
    {                                                                         \
        _Pragma("unroll")                                                     \
        for (int p = 0; p < 4; p++){                                          \
            cp16(As + p*128 + tid, AB + p*128 + tid);                         \
            cp16(Bs + p*128 + tid, BB + p*128 + tid);                         \
        }                                                                     \
        asm volatile("cp.async.commit_group;" ::: "memory");                  \
        _Pragma("unroll")                                                     \
        for (int p = 0; p < 4; p++){                                          \
            cp16(As + 512 + p*128 + tid, AB + 512 + p*128 + tid);             \
            cp16(Bs + 512 + p*128 + tid, BB + 512 + p*128 + tid);             \
        }                                                                     \
        asm volatile("cp.async.commit_group;" ::: "memory");                  \
    }                                                                         \
    int buf = 0;                                                              \
    for (int it = 0; it < (NITER); ++it){                                     \
        asm volatile("cp.async.wait_group 1;" ::: "memory");                  \
        __syncthreads();                                                      \
        _Pragma("unroll")                                                     \
        for (int ktl = 0; ktl < 2; ++ktl){                                    \
            const uint4* as = &As[buf*512 + ktl*256];                         \
            const uint4* bs = &Bs[buf*512 + ktl*256];                         \
            uint4 af[4]; uint2 bf[8];                                         \
            _Pragma("unroll")                                                 \
            for (int mi = 0; mi < 4; ++mi)                                    \
                af[mi] = as[(wmsub + mi)*32 + lane];                          \
            _Pragma("unroll")                                                 \
            for (int ni = 0; ni < 8; ++ni)                                    \
                bf[ni] = *(const uint2*)((const uint32_t*)bs                  \
                                         + (wnsub + ni)*64 + lane*2);         \
            _Pragma("unroll")                                                 \
            for (int mi = 0; mi < 4; ++mi)                                    \
                _Pragma("unroll")                                             \
                for (int ni = 0; ni < 8; ++ni)                                \
                    mma16(c[mi][ni], af[mi].x, af[mi].z, af[mi].y, af[mi].w,  \
                          bf[ni].x, bf[ni].y);                                \
        }                                                                     \
        if (it + 2 < (NITER)){                                                \
            int nbuf = buf + 2; if (nbuf >= 3) nbuf -= 3;                     \
            const uint4* sa = AB + (size_t)(it+2)*512;                        \
            const uint4* sb = BB + (size_t)(it+2)*512;                        \
            _Pragma("unroll")                                                 \
            for (int p = 0; p < 4; p++){                                      \
                cp16(As + nbuf*512 + p*128 + tid, sa + p*128 + tid);          \
                cp16(Bs + nbuf*512 + p*128 + tid, sb + p*128 + tid);          \
            }                                                                 \
        }                                                                     \
        asm volatile("cp.async.commit_group;" ::: "memory");                  \
        buf = (buf + 1 == 3) ? 0 : buf + 1;                                   \
    }

// ---------------- G partials: Gp[kc] = Em^T @ X over t-chunk kc --------------
__global__ __launch_bounds__(128)
void gemm_g_kernel(const uint4* __restrict__ Apk, const uint4* __restrict__ Bpk){
    __shared__ uint4 SM[3072];
    uint4* As = SM;
    uint4* Bs = SM + 1536;
    const int nb = blockIdx.x;                 // 0..7 (D blocks)
    const int b  = blockIdx.y >> 3, kc = blockIdx.y & 7;
    const uint4* Abase = Apk + ((size_t)b*512 + kc*64)*256;
    const uint4* Bbase = Bpk + (((size_t)(b*8 + nb)*512) + kc*64)*256;

    GEMM_CORE(Abase, Bbase, 32)

    const int gr = lane >> 2, gc = lane & 3;
    const int wm = (w >> 1) * 64, wn = (w & 1) * 64;
    float* Gp = g_Gp + (size_t)kc * (B_*L_*D_);
    #pragma unroll
    for (int mi = 0; mi < 4; ++mi){
        int hl = wm + mi*16 + gr;
        #pragma unroll
        for (int ni = 0; ni < 8; ++ni){
            int Dc = nb*128 + wn + ni*8 + gc*2;
            float* gp = &Gp[((size_t)b*128 + hl)*1024 + Dc];
            *reinterpret_cast<float2*>(gp)
                = make_float2(c[mi][ni][0], c[mi][ni][1]);
            *reinterpret_cast<float2*>(gp + 8*1024)
                = make_float2(c[mi][ni][2], c[mi][ni][3]);
        }
    }
}

// ---------------- Kv += (sum_p Gp_quarter @ Wv_head)  (256 CTAs, atomics) ----
__global__ __launch_bounds__(256)
void kvz1_kernel(const float* __restrict__ Wv){
    const int bh = blockIdx.x >> 2;      // b*16 + h
    const int dq = blockIdx.x & 3;       // Dc quarter (256 wide)
    const int b = bh >> 4, h = bh & 15;
    __shared__ float Gs[8][256];         // 8 KB
    __shared__ float red[4][8][64];      // 8 KB
    const int tid = threadIdx.x;

    for (int i = tid; i < 8*256; i += 256){
        int l = i >> 8, j = i & 255;
        size_t off = ((size_t)b*128 + h*8 + l)*1024 + dq*256 + j;
        float s = 0.f;
        #pragma unroll
        for (int p = 0; p < GP_; ++p)
            s += g_Gp[(size_t)p*(B_*L_*D_) + off];
        Gs[l][j] = s;
    }
    __syncthreads();

    const int d = tid & 63, lg4 = tid >> 6;   // 4 sub-chunks of 64 Dc
    float acc[8];
    #pragma unroll
    for (int l = 0; l < 8; ++l) acc[l] = 0.f;
    const float* wcol = Wv + h*64 + d + (size_t)dq*256*1024;
    #pragma unroll 8
    for (int j = 0; j < 64; ++j){
        int Dcl = lg4*64 + j;
        float wv = __ldg(wcol + (size_t)Dcl*1024);
        #pragma unroll
        for (int l = 0; l < 8; ++l) acc[l] += Gs[l][Dcl] * wv;
    }
    #pragma unroll
    for (int l = 0; l < 8; ++l) red[lg4][l][d] = acc[l];
    __syncthreads();

    if (tid < 64){
        #pragma unroll
        for (int l = 0; l < 8; ++l){
            float s = red[0][l][tid] + red[1][l][tid]
                    + red[2][l][tid] + red[3][l][tid];
            atomicAdd(&g_Kv[(bh*8 + l)*64 + tid], s);
        }
    }
}

// ---------------- Z[b,(h,l),n] = sum_d (Kv/Ksum)[b,h,l,d] * Po[h*64+d, n] ----
__global__ __launch_bounds__(256)
void z_kernel(const float* __restrict__ Po){
    int bid = blockIdx.x;           // b*64 + h*4 + nc
    int b = bid >> 6, h = (bid >> 2) & 15, nc = bid & 3;
    int tid = threadIdx.x;

    __shared__ float kvn[8][64];
    for (int j = tid; j < 512; j += 256){
        int l = j >> 6, d = j & 63;
        kvn[l][d] = g_Kv[((b*16 + h)*8 + l)*64 + d]
                  / g_Ksum[b*128 + h*8 + l];
    }
    __syncthreads();

    int n = nc*256 + tid;
    float acc[8];
    #pragma unroll
    for (int l = 0; l < 8; ++l) acc[l] = 0.f;
    #pragma unroll 8
    for (int d = 0; d < 64; ++d){
        float po = __ldg(Po + (size_t)(h*64 + d)*1024 + n);
        #pragma unroll
        for (int l = 0; l < 8; ++l) acc[l] += kvn[l][d] * po;
    }

    int nbk = n >> 7, nsub = (n & 127) >> 3, gr = n & 7;
    int kt = h >> 1, k8 = h & 1;
    uint32_t* out = (uint32_t*)g_Z;
    size_t base = (((size_t)(b*8 + nbk)*8 + kt)*16 + nsub)*64 + gr*8 + k8;
    #pragma unroll
    for (int j2 = 0; j2 < 4; ++j2)
        out[base + j2*2] = f2h2(acc[2*j2], acc[2*j2+1]);
}

// ---------------- GEMM2: out = Qs @ Z_b  (K=128) -----------------------------
__global__ __launch_bounds__(128)
void gemm2_kernel(const uint4* __restrict__ Apk, const uint4* __restrict__ Bpk,
                  float* __restrict__ C){
    __shared__ uint4 SM[3072];
    uint4* As = SM;
    uint4* Bs = SM + 1536;
    const int nb = blockIdx.x, mb = blockIdx.y;
    const uint4* Abase = Apk + (size_t)mb * 8 * 256;
    const uint4* Bbase = Bpk + (size_t)(mb >> 6) * 16384
                             + (size_t)nb * 8 * 256;

    GEMM_CORE(Abase, Bbase, 4)

    const int gr = lane >> 2, gc = lane & 3;
    const int wm = (w >> 1) * 64, wn = (w & 1) * 64;
    #pragma unroll
    for (int mi = 0; mi < 4; ++mi){
        int r0 = mb*128 + wm + mi*16 + gr;
        #pragma unroll
        for (int ni = 0; ni < 8; ++ni){
            int c0 = nb*128 + wn + ni*8 + gc*2;
            *reinterpret_cast<float2*>(&C[(size_t)r0*D_ + c0])
                = make_float2(c[mi][ni][0], c[mi][ni][1]);
            *reinterpret_cast<float2*>(&C[(size_t)(r0+8)*D_ + c0])
                = make_float2(c[mi][ni][2], c[mi][ni][3]);
        }
    }
}

// ---------------- launch -----------------------------------------------------
extern "C" void kernel_launch(void* const* d_in, const int* in_sizes, int n_in,
                              void* d_out, int out_size){
    const float* X    = (const float*)d_in[0];
    const float* mask = (const float*)d_in[1];
    const float* Wk   = (const float*)d_in[2];
    const float* Wq   = (const float*)d_in[3];
    const float* Wv   = (const float*)d_in[4];
    const float* Po   = (const float*)d_in[5];
    float* out = (float*)d_out;

    void *pXpk, *pXT, *pWpk, *pET, *pQs, *pZ;
    cudaGetSymbolAddress(&pXpk, g_Xpk);
    cudaGetSymbolAddress(&pXT,  g_XT);
    cudaGetSymbolAddress(&pWpk, g_Wpk);
    cudaGetSymbolAddress(&pET,  g_ET);
    cudaGetSymbolAddress(&pQs,  g_Qs);
    cudaGetSymbolAddress(&pZ,   g_Z);

    static cudaStream_t s1 = nullptr;
    static cudaEvent_t evFork = nullptr, evQ = nullptr;
    if (!s1){
        cudaStreamCreateWithFlags(&s1, cudaStreamNonBlocking);
        cudaEventCreateWithFlags(&evFork, cudaEventDisableTiming);
        cudaEventCreateWithFlags(&evQ,   cudaEventDisableTiming);
    }

    pack_xc_kernel<<<(R_/64)*(D_/128), 256>>>(X);
    prep_w_kernel<<<64, 256>>>(Wk, Wq);

    // fork: Q half of GEMM1 runs on side stream; only gemm2 needs its output
    cudaEventRecord(evFork, 0);
    cudaStreamWaitEvent(s1, evFork, 0);
    gemm1_kernel<<<dim3(2, R_/128), 128, 0, s1>>>((const uint4*)pXpk,
                                                  (const uint4*)pWpk, mask, 2);
    cudaEventRecord(evQ, s1);

    // main: E half -> gemm_g -> kvz1 -> z (critical path)
    gemm1_kernel<<<dim3(2, R_/128), 128>>>((const uint4*)pXpk,
                                           (const uint4*)pWpk, mask, 0);

    gemm_g_kernel<<<dim3(8, B_*GP_), 128>>>((const uint4*)pET,
                                            (const uint4*)pXT);

    kvz1_kernel<<<B_*H_*4, 256>>>(Wv);
    z_kernel<<<B_*H_*4, 256>>>(Po);

    // join: gemm2 needs Qs (side stream) and Z (main)
    cudaStreamWaitEvent(0, evQ, 0);
    gemm2_kernel<<<dim3(8, R_/128), 128>>>((const uint4*)pQs,
                                           (const uint4*)pZ, out);
}